// round 2
// baseline (speedup 1.0000x reference)
#include <cuda_runtime.h>

// HierarchicalConsistencyLoss:
//   diff = offset_inst - offset_tree            (coords cancels)
//   per-tree mean of diff over points with label>0
//   loss = sum_t ||mean_t||^2 * [count_t >= 2] / n_trees,  n_trees = #{t: count_t >= 1}
//
// Pass 1: zero scratch.  Pass 2: per-CTA shared-memory segment sums -> global atomics.
// Pass 3: single-block finalize.

#define T_MAX 1000

// scratch: [T_MAX][4] = {sum_dx, sum_dy, sum_dz, count}
__device__ float g_acc[T_MAX * 4];

__global__ void hcl_zero_kernel() {
    int i = blockIdx.x * blockDim.x + threadIdx.x;
    if (i < T_MAX * 4) g_acc[i] = 0.0f;
}

__global__ void __launch_bounds__(256) hcl_accum_kernel(
    const float* __restrict__ oi,    // offset_inst, [N*3]
    const float* __restrict__ ot,    // offset_tree, [N*3]
    const int*   __restrict__ lab,   // tree_labels, [N]
    int n)
{
    __shared__ float s[T_MAX * 4];
    for (int i = threadIdx.x; i < T_MAX * 4; i += blockDim.x) s[i] = 0.0f;
    __syncthreads();

    const int stride = gridDim.x * blockDim.x;
    for (int i = blockIdx.x * blockDim.x + threadIdx.x; i < n; i += stride) {
        int l = __ldg(&lab[i]);
        // label 0 = invalid/stuff: zero weight
        if (l > 0) {
            int b = 3 * i;
            float dx = oi[b + 0] - ot[b + 0];
            float dy = oi[b + 1] - ot[b + 1];
            float dz = oi[b + 2] - ot[b + 2];
            int o = l * 4;
            atomicAdd(&s[o + 0], dx);
            atomicAdd(&s[o + 1], dy);
            atomicAdd(&s[o + 2], dz);
            atomicAdd(&s[o + 3], 1.0f);
        }
    }
    __syncthreads();

    // flush per-CTA partials to global scratch
    for (int i = threadIdx.x; i < T_MAX * 4; i += blockDim.x) {
        float v = s[i];
        if (v != 0.0f) atomicAdd(&g_acc[i], v);
    }
}

__global__ void __launch_bounds__(1024) hcl_finalize_kernel(float* __restrict__ out) {
    __shared__ float red_t[32];
    __shared__ float red_n[32];

    int t = threadIdx.x;
    float total = 0.0f, ntrees = 0.0f;

    for (int i = t; i < T_MAX; i += blockDim.x) {
        float c = g_acc[i * 4 + 3];
        if (c >= 1.0f) {
            ntrees += 1.0f;
            if (c >= 2.0f) {
                float inv = 1.0f / c;   // c >= 1, so max(c,1) == c
                float mx = g_acc[i * 4 + 0] * inv;
                float my = g_acc[i * 4 + 1] * inv;
                float mz = g_acc[i * 4 + 2] * inv;
                total += mx * mx + my * my + mz * mz;
            }
        }
    }

    // warp reduce
    #pragma unroll
    for (int off = 16; off > 0; off >>= 1) {
        total  += __shfl_down_sync(0xFFFFFFFFu, total,  off);
        ntrees += __shfl_down_sync(0xFFFFFFFFu, ntrees, off);
    }
    int wid = t >> 5, lid = t & 31;
    if (lid == 0) { red_t[wid] = total; red_n[wid] = ntrees; }
    __syncthreads();

    if (wid == 0) {
        int nw = blockDim.x >> 5;
        total  = (lid < nw) ? red_t[lid] : 0.0f;
        ntrees = (lid < nw) ? red_n[lid] : 0.0f;
        #pragma unroll
        for (int off = 16; off > 0; off >>= 1) {
            total  += __shfl_down_sync(0xFFFFFFFFu, total,  off);
            ntrees += __shfl_down_sync(0xFFFFFFFFu, ntrees, off);
        }
        if (lid == 0) out[0] = (ntrees > 0.0f) ? (total / ntrees) : 0.0f;
    }
}

extern "C" void kernel_launch(void* const* d_in, const int* in_sizes, int n_in,
                              void* d_out, int out_size) {
    // inputs (metadata order): coords [N*3] (UNUSED), offset_inst [N*3],
    //                          offset_tree [N*3], tree_labels [N]
    const float* oi  = (const float*)d_in[1];
    const float* ot  = (const float*)d_in[2];
    const int*   lab = (const int*)d_in[3];
    float* out = (float*)d_out;
    int n = in_sizes[3];

    hcl_zero_kernel<<<(T_MAX * 4 + 255) / 256, 256>>>();

    // ~10 CTAs/SM on 148 SMs for latency hiding
    int blocks = 148 * 10;
    int max_blocks = (n + 255) / 256;
    if (blocks > max_blocks) blocks = max_blocks;
    hcl_accum_kernel<<<blocks, 256>>>(oi, ot, lab, n);

    hcl_finalize_kernel<<<1, 1024>>>(out);
}

// round 3
// speedup vs baseline: 1.6453x; 1.6453x over previous
#include <cuda_runtime.h>

// HierarchicalConsistencyLoss:
//   diff = offset_inst - offset_tree            (coords cancels)
//   per-tree mean over points with label>0
//   loss = sum_t ||mean_t||^2 * [count_t >= 2] / n_trees,  n_trees = #{t: count_t >= 1}
//
// Strategy: one red.global.add.v4.f32 per valid point into an L2-resident
// scratch table. Bins padded to 128B (own L2 line) and replicated x8 to keep
// every LTS slice's atomic ALU pipelined. No shared-memory atomics at all.

#define T_MAX   1000
#define NREP    8            // replicas per tree
#define SLOT_F  32           // floats per (tree, replica) slot = 128 bytes
#define SCRATCH_F (T_MAX * NREP * SLOT_F)   // 256000 floats = 1 MB

__device__ float g_acc[SCRATCH_F];

__global__ void hcl_zero_kernel() {
    int i = blockIdx.x * blockDim.x + threadIdx.x;
    // zero only the live float4 at the head of each 128B slot
    if (i < T_MAX * NREP) {
        float4* p = reinterpret_cast<float4*>(&g_acc[i * SLOT_F]);
        *p = make_float4(0.f, 0.f, 0.f, 0.f);
    }
}

__device__ __forceinline__ void red_v4(float* addr, float x, float y, float z, float w) {
    asm volatile("red.global.add.v4.f32 [%0], {%1, %2, %3, %4};"
                 :: "l"(addr), "f"(x), "f"(y), "f"(z), "f"(w) : "memory");
}

__device__ __forceinline__ void accum_point(int l, float dx, float dy, float dz, int rep) {
    if (l > 0) {
        float* addr = &g_acc[(l * NREP + rep) * SLOT_F];
        red_v4(addr, dx, dy, dz, 1.0f);
    }
}

__global__ void __launch_bounds__(256) hcl_accum_kernel(
    const float* __restrict__ oi,    // offset_inst, [N*3]
    const float* __restrict__ ot,    // offset_tree, [N*3]
    const int*   __restrict__ lab,   // tree_labels, [N]
    int n)
{
    const int tid = blockIdx.x * blockDim.x + threadIdx.x;
    const int rep = (int)(((unsigned)(tid >> 5)) & (NREP - 1));  // spread per warp
    const int base = tid * 4;

    if (base + 3 < n) {
        int4 l4 = reinterpret_cast<const int4*>(lab)[tid];
        const float4* oi4 = reinterpret_cast<const float4*>(oi);
        const float4* ot4 = reinterpret_cast<const float4*>(ot);
        float4 a0 = oi4[3 * tid + 0], a1 = oi4[3 * tid + 1], a2 = oi4[3 * tid + 2];
        float4 b0 = ot4[3 * tid + 0], b1 = ot4[3 * tid + 1], b2 = ot4[3 * tid + 2];

        accum_point(l4.x, a0.x - b0.x, a0.y - b0.y, a0.z - b0.z, rep);
        accum_point(l4.y, a0.w - b0.w, a1.x - b1.x, a1.y - b1.y, rep);
        accum_point(l4.z, a1.z - b1.z, a1.w - b1.w, a2.x - b2.x, rep);
        accum_point(l4.w, a2.y - b2.y, a2.z - b2.z, a2.w - b2.w, rep);
    } else {
        // tail (and any partial vector) — scalar path
        for (int i = base; i < n && i < base + 4; i++) {
            int l = lab[i];
            if (l > 0) {
                int b = 3 * i;
                accum_point(l, oi[b + 0] - ot[b + 0],
                               oi[b + 1] - ot[b + 1],
                               oi[b + 2] - ot[b + 2], rep);
            }
        }
    }
}

__global__ void __launch_bounds__(1024) hcl_finalize_kernel(float* __restrict__ out) {
    __shared__ float red_t[32];
    __shared__ float red_n[32];

    int t = threadIdx.x;
    float total = 0.0f, ntrees = 0.0f;

    for (int i = t; i < T_MAX; i += blockDim.x) {
        float sx = 0.f, sy = 0.f, sz = 0.f, c = 0.f;
        #pragma unroll
        for (int r = 0; r < NREP; r++) {
            const float4 v = *reinterpret_cast<const float4*>(
                &g_acc[(i * NREP + r) * SLOT_F]);
            sx += v.x; sy += v.y; sz += v.z; c += v.w;
        }
        if (c >= 1.0f) {
            ntrees += 1.0f;
            if (c >= 2.0f) {
                float inv = 1.0f / c;   // c >= 1 so max(c,1) == c
                float mx = sx * inv, my = sy * inv, mz = sz * inv;
                total += mx * mx + my * my + mz * mz;
            }
        }
    }

    #pragma unroll
    for (int off = 16; off > 0; off >>= 1) {
        total  += __shfl_down_sync(0xFFFFFFFFu, total,  off);
        ntrees += __shfl_down_sync(0xFFFFFFFFu, ntrees, off);
    }
    int wid = t >> 5, lid = t & 31;
    if (lid == 0) { red_t[wid] = total; red_n[wid] = ntrees; }
    __syncthreads();

    if (wid == 0) {
        int nw = blockDim.x >> 5;
        total  = (lid < nw) ? red_t[lid] : 0.0f;
        ntrees = (lid < nw) ? red_n[lid] : 0.0f;
        #pragma unroll
        for (int off = 16; off > 0; off >>= 1) {
            total  += __shfl_down_sync(0xFFFFFFFFu, total,  off);
            ntrees += __shfl_down_sync(0xFFFFFFFFu, ntrees, off);
        }
        if (lid == 0) out[0] = (ntrees > 0.0f) ? (total / ntrees) : 0.0f;
    }
}

extern "C" void kernel_launch(void* const* d_in, const int* in_sizes, int n_in,
                              void* d_out, int out_size) {
    // inputs (metadata order): coords [N*3] (UNUSED), offset_inst [N*3],
    //                          offset_tree [N*3], tree_labels [N]
    const float* oi  = (const float*)d_in[1];
    const float* ot  = (const float*)d_in[2];
    const int*   lab = (const int*)d_in[3];
    float* out = (float*)d_out;
    int n = in_sizes[3];

    hcl_zero_kernel<<<(T_MAX * NREP + 255) / 256, 256>>>();

    int nthreads = (n + 3) / 4;                 // 4 points per thread
    int blocks = (nthreads + 255) / 256;
    hcl_accum_kernel<<<blocks, 256>>>(oi, ot, lab, n);

    hcl_finalize_kernel<<<1, 1024>>>(out);
}